// round 7
// baseline (speedup 1.0000x reference)
#include <cuda_runtime.h>
#include <cuda_bf16.h>
#include <cstdint>

// Problem constants
#define BB 8
#define NN 2048
#define DD 256
#define LL 2
#define MROWS (BB * NN)   // 16384

#define KC 64             // K per pipeline chunk
#define NSTAGES 3

// smem geometry (padded, no swizzle)
#define PADK 72                      // 64 + 8 bf16 pad
#define ROWB (PADK * 2)              // 144 bytes per row

// xw kernel (128x128 tiles)
#define ASTAGE (128 * ROWB)          // 18432 B
#define STAGE_BYTES (2 * ASTAGE)     // 36864 B
#define MMA_SMEM (NSTAGES * STAGE_BYTES)  // 110592 B

// nn kernel (128x256 tiles)
#define A2STAGE (128 * ROWB)         // 18432 B
#define B2STAGE (256 * ROWB)         // 36864 B
#define STAGE2 (A2STAGE + B2STAGE)   // 55296 B
#define NN2_SMEM (NSTAGES * STAGE2)  // 165888 B

// ---------------------------------------------------------------------------
// Scratch (static __device__ arrays — no allocation allowed)
// ---------------------------------------------------------------------------
__device__ __nv_bfloat16 g_nodes_bf[(size_t)MROWS * DD];    // nodes bf16
__device__ __nv_bfloat16 g_xbf[(size_t)MROWS * DD];         // activations bf16
__device__ __nv_bfloat16 g_xWrT[(size_t)BB * DD * NN];      // (x@Wr^T+br)^T bf16
__device__ __nv_bfloat16 g_W0bf[(size_t)LL * DD * DD];      // W0_w bf16
__device__ __nv_bfloat16 g_Wrbf[(size_t)LL * DD * DD];      // Wr_w bf16
__device__ float g_xW0[(size_t)MROWS * DD];                 // x @ W0^T + b0 (fp32)

// ---------------------------------------------------------------------------
// PTX helpers (plain-sm_103-safe)
// ---------------------------------------------------------------------------
__device__ __forceinline__ uint32_t smem_u32(const void* p) {
    uint32_t a;
    asm("{ .reg .u64 t; cvta.to.shared.u64 t, %1; cvt.u32.u64 %0, t; }" : "=r"(a) : "l"(p));
    return a;
}
__device__ __forceinline__ void cp_async16(uint32_t saddr, const void* g) {
    asm volatile("cp.async.cg.shared.global [%0], [%1], 16;" :: "r"(saddr), "l"(g) : "memory");
}
__device__ __forceinline__ void cp_commit() {
    asm volatile("cp.async.commit_group;" ::: "memory");
}
template <int N>
__device__ __forceinline__ void cp_wait() {
    asm volatile("cp.async.wait_group %0;" :: "n"(N) : "memory");
}
__device__ __forceinline__ void ldsm_x4(uint32_t (&r)[4], uint32_t addr) {
    asm volatile("ldmatrix.sync.aligned.m8n8.x4.shared.b16 {%0,%1,%2,%3}, [%4];"
                 : "=r"(r[0]), "=r"(r[1]), "=r"(r[2]), "=r"(r[3]) : "r"(addr));
}
__device__ __forceinline__ void mma_bf16(float (&c)[4], const uint32_t (&a)[4],
                                         uint32_t b0, uint32_t b1) {
    asm volatile(
        "mma.sync.aligned.m16n8k16.row.col.f32.bf16.bf16.f32 "
        "{%0,%1,%2,%3}, {%4,%5,%6,%7}, {%8,%9}, {%0,%1,%2,%3};"
        : "+f"(c[0]), "+f"(c[1]), "+f"(c[2]), "+f"(c[3])
        : "r"(a[0]), "r"(a[1]), "r"(a[2]), "r"(a[3]), "r"(b0), "r"(b1));
}
__device__ __forceinline__ uint32_t pack_bf16x2(float x, float y) {
    __nv_bfloat162 v = __floats2bfloat162_rn(x, y);
    return *(uint32_t*)&v;
}
__device__ __forceinline__ void sts128(uint32_t addr, uint32_t a, uint32_t b,
                                       uint32_t c, uint32_t d) {
    asm volatile("st.shared.v4.b32 [%0], {%1,%2,%3,%4};"
                 :: "r"(addr), "r"(a), "r"(b), "r"(c), "r"(d) : "memory");
}

// ---------------------------------------------------------------------------
// prep: nodes + weight matrices -> bf16 (8 fp32 per thread)
// ---------------------------------------------------------------------------
#define NB_NODES ((MROWS * DD) / (256 * 8))           // 2048
#define NB_W ((LL * DD * DD) / (256 * 8))             // 64

__global__ void convert_prep_kernel(const float* __restrict__ nodes,
                                    const float* __restrict__ W0w,
                                    const float* __restrict__ Wrw) {
    int bid = blockIdx.x;
    const float* src;
    __nv_bfloat16* dst;
    size_t off;
    if (bid < NB_NODES) {
        src = nodes; dst = g_nodes_bf; off = (size_t)bid * 256 * 8;
    } else if (bid < NB_NODES + NB_W) {
        src = W0w; dst = g_W0bf; off = (size_t)(bid - NB_NODES) * 256 * 8;
    } else {
        src = Wrw; dst = g_Wrbf; off = (size_t)(bid - NB_NODES - NB_W) * 256 * 8;
    }
    size_t p = off + (size_t)threadIdx.x * 8;
    float4 v0 = *(const float4*)(src + p);
    float4 v1 = *(const float4*)(src + p + 4);
    __nv_bfloat16 tmp[8];
    tmp[0] = __float2bfloat16(v0.x); tmp[1] = __float2bfloat16(v0.y);
    tmp[2] = __float2bfloat16(v0.z); tmp[3] = __float2bfloat16(v0.w);
    tmp[4] = __float2bfloat16(v1.x); tmp[5] = __float2bfloat16(v1.y);
    tmp[6] = __float2bfloat16(v1.z); tmp[7] = __float2bfloat16(v1.w);
    *(uint4*)(dst + p) = *(const uint4*)tmp;
}

// ---------------------------------------------------------------------------
// Fused NT GEMM on mma.sync: x@W0^T+b0 (fp32) and x@Wr^T+br (bf16, transposed)
//   grid = (4, 128), block = 256 (8 warps: 4M x 2N)
// ---------------------------------------------------------------------------
__global__ void __launch_bounds__(256, 2)
xw_mma_kernel(int use_x,
              const float* __restrict__ b0,
              const float* __restrict__ br,
              int layer) {
    extern __shared__ char smem[];
    uint32_t sb = smem_u32(smem);
    __nv_bfloat16* Ts = (__nv_bfloat16*)smem;

    int tid = threadIdx.x;
    int lane = tid & 31, wid = tid >> 5;
    int warp_m = wid & 3, warp_n = wid >> 2;
    int row0 = blockIdx.y * 128;
    int is_wr = (blockIdx.x >= 2);
    int colt = blockIdx.x & 1;
    int col0w = colt * 128;

    const __nv_bfloat16* Abase = use_x ? g_xbf : g_nodes_bf;
    const __nv_bfloat16* Ag = Abase + (size_t)row0 * DD;
    const __nv_bfloat16* Bg = (is_wr ? g_Wrbf : g_W0bf) + (size_t)layer * DD * DD
                              + (size_t)col0w * DD;

    float acc[2][8][4];
#pragma unroll
    for (int i = 0; i < 2; ++i)
#pragma unroll
        for (int j = 0; j < 8; ++j)
#pragma unroll
            for (int q = 0; q < 4; ++q) acc[i][j][q] = 0.f;

    uint32_t a_base = sb + (uint32_t)((warp_m * 32 + (lane & 15)) * ROWB + (lane >> 4) * 16);
    uint32_t b_base = sb + ASTAGE +
                      (uint32_t)((warp_n * 64 + (lane & 15)) * ROWB + (lane >> 4) * 16);

    auto load_stage = [&](int c, int s) {
        uint32_t as = sb + s * STAGE_BYTES;
        uint32_t bs = as + ASTAGE;
        int k0 = c * KC;
#pragma unroll
        for (int i = 0; i < 4; ++i) {
            int idx = i * 256 + tid;
            int r = idx >> 3, ch = idx & 7;
            cp_async16(as + r * ROWB + ch * 16, Ag + (size_t)r * DD + k0 + ch * 8);
        }
#pragma unroll
        for (int i = 0; i < 4; ++i) {
            int idx = i * 256 + tid;
            int r = idx >> 3, ch = idx & 7;
            cp_async16(bs + r * ROWB + ch * 16, Bg + (size_t)r * DD + k0 + ch * 8);
        }
        cp_commit();
    };

    auto compute_stage = [&](int s) {
        uint32_t as = a_base + s * STAGE_BYTES;
        uint32_t bs = b_base + s * STAGE_BYTES;
#pragma unroll
        for (int ks = 0; ks < 4; ++ks) {
            uint32_t af[2][4];
            ldsm_x4(af[0], as + 0 * 16 * ROWB + ks * 32);
            ldsm_x4(af[1], as + 1 * 16 * ROWB + ks * 32);
            uint32_t bf[4][4];
#pragma unroll
            for (int n2 = 0; n2 < 4; ++n2)
                ldsm_x4(bf[n2], bs + n2 * 16 * ROWB + ks * 32);
#pragma unroll
            for (int mf = 0; mf < 2; ++mf)
#pragma unroll
                for (int nf = 0; nf < 8; ++nf)
                    mma_bf16(acc[mf][nf], af[mf], bf[nf >> 1][nf & 1],
                             bf[nf >> 1][(nf & 1) + 2]);
        }
    };

    load_stage(0, 0);
    load_stage(1, 1);
    for (int c = 0; c < 4; ++c) {
        if (c + 1 < 4) cp_wait<1>(); else cp_wait<0>();
        __syncthreads();
        if (c + 2 < 4) load_stage(c + 2, (c + 2) % NSTAGES);
        compute_stage(c % NSTAGES);
    }

    const float* bias = (is_wr ? br : b0);
    int g = lane >> 2, tg = lane & 3;

    if (!is_wr) {
#pragma unroll
        for (int mf = 0; mf < 2; ++mf)
#pragma unroll
            for (int half = 0; half < 2; ++half) {
                int row = row0 + warp_m * 32 + mf * 16 + half * 8 + g;
#pragma unroll
                for (int nf = 0; nf < 8; ++nf) {
                    int col = col0w + warp_n * 64 + nf * 8 + tg * 2;
                    float2 bi = *(const float2*)(bias + col);
                    float2 r;
                    r.x = acc[mf][nf][half * 2 + 0] + bi.x;
                    r.y = acc[mf][nf][half * 2 + 1] + bi.y;
                    *(float2*)(g_xW0 + (size_t)row * DD + col) = r;
                }
            }
    } else {
        __syncthreads();
#pragma unroll
        for (int mf = 0; mf < 2; ++mf)
#pragma unroll
            for (int half = 0; half < 2; ++half) {
                int rl = warp_m * 32 + mf * 16 + half * 8 + g;
#pragma unroll
                for (int nf = 0; nf < 8; ++nf) {
                    int cl = warp_n * 64 + nf * 8 + tg * 2;
                    float2 bi = *(const float2*)(bias + col0w + cl);
                    Ts[(size_t)cl * 136 + rl] =
                        __float2bfloat16(acc[mf][nf][half * 2 + 0] + bi.x);
                    Ts[(size_t)(cl + 1) * 136 + rl] =
                        __float2bfloat16(acc[mf][nf][half * 2 + 1] + bi.y);
                }
            }
        __syncthreads();
        int b = row0 >> 11;
        int nloc = row0 & 2047;
        int dl = tid >> 1, seg = tid & 1;
        __nv_bfloat16* dst = g_xWrT + (size_t)b * DD * NN + (size_t)(col0w + dl) * NN
                             + nloc + seg * 64;
        const __nv_bfloat16* srcp = Ts + (size_t)dl * 136 + seg * 64;
#pragma unroll
        for (int q = 0; q < 8; ++q)
            *(uint4*)(dst + q * 8) = *(const uint4*)(srcp + q * 8);
    }
}

// ---------------------------------------------------------------------------
// NN GEMM on mma.sync, 128x256 tile, in-kernel adj fp32->bf16 + denom rowsum
//   A = adj fp32 (LDG->cvt->STS, reg double-buffered one chunk ahead)
//   B = g_xWrT bf16 (3-stage cp.async)
//   grid = (NN/128=16, BB=8) = 128 CTAs (single wave), block = 256
// ---------------------------------------------------------------------------
#define NCHUNK (NN / KC)  // 32

__global__ void __launch_bounds__(256, 1)
nn_mma_kernel(const float* __restrict__ adj, const float* __restrict__ nodes,
              float* __restrict__ dout, int final_layer) {
    extern __shared__ char smem[];
    __shared__ float red[256];
    __shared__ float denomarr[128];
    uint32_t sb = smem_u32(smem);

    int tid = threadIdx.x;
    int lane = tid & 31, wid = tid >> 5;
    int warp_m = wid & 3, warp_n = wid >> 2;    // 4M x 2N warps
    int row0 = blockIdx.x * 128;
    int b = blockIdx.y;

    const float* Ag = adj + (size_t)b * NN * NN + (size_t)row0 * NN;
    const __nv_bfloat16* Bg = g_xWrT + (size_t)b * DD * NN;

    float acc[2][16][4];
#pragma unroll
    for (int i = 0; i < 2; ++i)
#pragma unroll
        for (int j = 0; j < 16; ++j)
#pragma unroll
            for (int q = 0; q < 4; ++q) acc[i][j][q] = 0.f;

    // A loader: thread pair per row; thread covers 32 contiguous floats
    int arow = tid >> 1;
    int ahalf = tid & 1;
    const float* arow_ptr = Ag + (size_t)arow * NN + ahalf * 32;
    uint32_t asts_base = sb + (uint32_t)(arow * ROWB + ahalf * 64);

    float rowsum = 0.f;
    float4 areg[8];

    auto ldgA = [&](int c) {
        const float4* p = (const float4*)(arow_ptr + c * KC);
#pragma unroll
        for (int q = 0; q < 8; ++q) areg[q] = p[q];
    };
    auto stsA = [&](int s) {
        uint32_t base = asts_base + s * STAGE2;
#pragma unroll
        for (int q = 0; q < 4; ++q) {
            float4 v0 = areg[q * 2], v1 = areg[q * 2 + 1];
            rowsum += v0.x + v0.y + v0.z + v0.w + v1.x + v1.y + v1.z + v1.w;
            sts128(base + q * 16,
                   pack_bf16x2(v0.x, v0.y), pack_bf16x2(v0.z, v0.w),
                   pack_bf16x2(v1.x, v1.y), pack_bf16x2(v1.z, v1.w));
        }
    };
    auto cpB = [&](int c, int s) {
        uint32_t bs = sb + s * STAGE2 + A2STAGE;
        int k0 = c * KC;
#pragma unroll
        for (int i = 0; i < 8; ++i) {           // 256 rows x 8 chunks of 16B
            int idx = i * 256 + tid;
            int r = idx >> 3, ch = idx & 7;
            cp_async16(bs + r * ROWB + ch * 16, Bg + (size_t)r * NN + k0 + ch * 8);
        }
        cp_commit();
    };

    uint32_t a_base = sb + (uint32_t)((warp_m * 32 + (lane & 15)) * ROWB + (lane >> 4) * 16);
    uint32_t b_base = sb + A2STAGE +
                      (uint32_t)((warp_n * 128 + (lane & 15)) * ROWB + (lane >> 4) * 16);

    auto compute = [&](int s) {
        uint32_t as = a_base + s * STAGE2;
        uint32_t bs = b_base + s * STAGE2;
#pragma unroll
        for (int ks = 0; ks < 4; ++ks) {
            uint32_t af[2][4];
            ldsm_x4(af[0], as + 0 * 16 * ROWB + ks * 32);
            ldsm_x4(af[1], as + 1 * 16 * ROWB + ks * 32);
#pragma unroll
            for (int n2 = 0; n2 < 8; ++n2) {
                uint32_t bf[4];
                ldsm_x4(bf, bs + n2 * 16 * ROWB + ks * 32);
#pragma unroll
                for (int mf = 0; mf < 2; ++mf) {
                    mma_bf16(acc[mf][n2 * 2 + 0], af[mf], bf[0], bf[2]);
                    mma_bf16(acc[mf][n2 * 2 + 1], af[mf], bf[1], bf[3]);
                }
            }
        }
    };

    // Prologue: stages 0,1 filled; A regs hold chunk 2
    ldgA(0); stsA(0); cpB(0, 0);
    ldgA(1); stsA(1); cpB(1, 1);
    ldgA(2);

    for (int c = 0; c < NCHUNK; ++c) {
        if (c + 1 < NCHUNK) cp_wait<1>(); else cp_wait<0>();
        __syncthreads();                         // stage c ready; stage (c+2)%3 free
        if (c + 2 < NCHUNK) {
            stsA((c + 2) % NSTAGES);             // from areg (chunk c+2)
            cpB(c + 2, (c + 2) % NSTAGES);
            if (c + 3 < NCHUNK) ldgA(c + 3);
        }
        compute(c % NSTAGES);
    }

    // denom reduce: pair partials per row
    red[tid] = rowsum;
    __syncthreads();
    if (tid < 128) denomarr[tid] = red[tid * 2] + red[tid * 2 + 1] + 1.0f;
    __syncthreads();

    // fused epilogue
    int g = lane >> 2, tg = lane & 3;
#pragma unroll
    for (int mf = 0; mf < 2; ++mf) {
#pragma unroll
        for (int half = 0; half < 2; ++half) {
            int rl = warp_m * 32 + mf * 16 + half * 8 + g;
            size_t grow = (size_t)b * NN + row0 + rl;
            float inv = 1.0f / denomarr[rl];
            const float* w0r = g_xW0 + grow * DD;
            const float* ndr = nodes + grow * DD;
            float* orr = dout + grow * DD;
            __nv_bfloat16* xr = g_xbf + grow * DD;
#pragma unroll
            for (int nf = 0; nf < 16; ++nf) {
                int col = warp_n * 128 + nf * 8 + tg * 2;
                float2 w0 = *(const float2*)(w0r + col);
                float vx = fmaxf((acc[mf][nf][half * 2 + 0] + w0.x) * inv, 0.f);
                float vy = fmaxf((acc[mf][nf][half * 2 + 1] + w0.y) * inv, 0.f);
                if (final_layer) {
                    float2 nd = *(const float2*)(ndr + col);
                    vx += nd.x; vy += nd.y;
                    *(float2*)(orr + col) = make_float2(vx, vy);
                } else {
                    *(uint32_t*)(xr + col) = pack_bf16x2(vx, vy);
                }
            }
        }
    }
}

// ---------------------------------------------------------------------------
// Launch
// ---------------------------------------------------------------------------
extern "C" void kernel_launch(void* const* d_in, const int* in_sizes, int n_in,
                              void* d_out, int out_size) {
    const float* nodes = (const float*)d_in[0];
    const float* adj   = (const float*)d_in[1];
    const float* W0w   = (const float*)d_in[2];
    const float* W0b   = (const float*)d_in[3];
    const float* Wrw   = (const float*)d_in[4];
    const float* Wrb   = (const float*)d_in[5];
    float* out = (float*)d_out;

    cudaFuncSetAttribute(nn_mma_kernel, cudaFuncAttributeMaxDynamicSharedMemorySize,
                         NN2_SMEM);
    cudaFuncSetAttribute(xw_mma_kernel, cudaFuncAttributeMaxDynamicSharedMemorySize,
                         MMA_SMEM);

    convert_prep_kernel<<<NB_NODES + 2 * NB_W, 256>>>(nodes, W0w, Wrw);

    dim3 grid_xw(4, MROWS / 128);          // (4, 128)
    dim3 grid_nn(NN / 128, BB);            // (16, 8) = 128 CTAs

    for (int l = 0; l < LL; ++l) {
        xw_mma_kernel<<<grid_xw, 256, MMA_SMEM>>>((l == 0) ? 0 : 1,
                                                  W0b + (size_t)l * DD,
                                                  Wrb + (size_t)l * DD, l);
        nn_mma_kernel<<<grid_nn, 256, NN2_SMEM>>>(adj, nodes, out,
                                                  (l == LL - 1) ? 1 : 0);
    }
}

// round 8
// speedup vs baseline: 1.0407x; 1.0407x over previous
#include <cuda_runtime.h>
#include <cuda_bf16.h>
#include <cstdint>

// Problem constants
#define BB 8
#define NN 2048
#define DD 256
#define LL 2
#define MROWS (BB * NN)   // 16384

#define KC 64             // K per pipeline chunk
#define NSTAGES 3

// smem geometry (padded, no swizzle)
#define PADK 72                      // 64 + 8 bf16 pad
#define ROWB (PADK * 2)              // 144 bytes per row
#define ASTAGE (128 * ROWB)          // 18432 B
#define STAGE_BYTES (2 * ASTAGE)     // 36864 B (A + B)
#define NN_SMEM (NSTAGES * STAGE_BYTES)  // 110592 B

// xw kernel: persistent B + 2-stage A
#define XW_A_STAGE (128 * ROWB)          // 18432
#define XW_B_OFF (2 * XW_A_STAGE)        // 36864
#define XW_B_STRIDE 528                  // 512B data + 16B pad
#define XW_SMEM (XW_B_OFF + 128 * XW_B_STRIDE)   // 104448 B  (2 CTA/SM)

// ---------------------------------------------------------------------------
// Scratch
// ---------------------------------------------------------------------------
__device__ __nv_bfloat16 g_adj_bf[(size_t)BB * NN * NN];    // adj bf16
__device__ __nv_bfloat16 g_nodes_bf[(size_t)MROWS * DD];    // nodes bf16
__device__ __nv_bfloat16 g_xbf[(size_t)MROWS * DD];         // activations bf16
__device__ __nv_bfloat16 g_xWrT[(size_t)BB * DD * NN];      // (x@Wr^T+br)^T bf16
__device__ __nv_bfloat16 g_W0bf[(size_t)LL * DD * DD];      // W0_w bf16
__device__ __nv_bfloat16 g_Wrbf[(size_t)LL * DD * DD];      // Wr_w bf16
__device__ float g_xW0[(size_t)MROWS * DD];                 // x @ W0^T + b0 (fp32)
__device__ float g_denom[MROWS];                            // row-sum(adj) + 1

// ---------------------------------------------------------------------------
// PTX helpers (plain-sm_103-safe)
// ---------------------------------------------------------------------------
__device__ __forceinline__ uint32_t smem_u32(const void* p) {
    uint32_t a;
    asm("{ .reg .u64 t; cvta.to.shared.u64 t, %1; cvt.u32.u64 %0, t; }" : "=r"(a) : "l"(p));
    return a;
}
__device__ __forceinline__ void cp_async16(uint32_t saddr, const void* g) {
    asm volatile("cp.async.cg.shared.global [%0], [%1], 16;" :: "r"(saddr), "l"(g) : "memory");
}
__device__ __forceinline__ void cp_commit() {
    asm volatile("cp.async.commit_group;" ::: "memory");
}
template <int N>
__device__ __forceinline__ void cp_wait() {
    asm volatile("cp.async.wait_group %0;" :: "n"(N) : "memory");
}
__device__ __forceinline__ void ldsm_x4(uint32_t (&r)[4], uint32_t addr) {
    asm volatile("ldmatrix.sync.aligned.m8n8.x4.shared.b16 {%0,%1,%2,%3}, [%4];"
                 : "=r"(r[0]), "=r"(r[1]), "=r"(r[2]), "=r"(r[3]) : "r"(addr));
}
__device__ __forceinline__ void mma_bf16(float (&c)[4], const uint32_t (&a)[4],
                                         uint32_t b0, uint32_t b1) {
    asm volatile(
        "mma.sync.aligned.m16n8k16.row.col.f32.bf16.bf16.f32 "
        "{%0,%1,%2,%3}, {%4,%5,%6,%7}, {%8,%9}, {%0,%1,%2,%3};"
        : "+f"(c[0]), "+f"(c[1]), "+f"(c[2]), "+f"(c[3])
        : "r"(a[0]), "r"(a[1]), "r"(a[2]), "r"(a[3]), "r"(b0), "r"(b1));
}
__device__ __forceinline__ uint32_t pack_bf16x2(float x, float y) {
    __nv_bfloat162 v = __floats2bfloat162_rn(x, y);
    return *(uint32_t*)&v;
}

// ---------------------------------------------------------------------------
// One conversion kernel for everything:
//   blocks [0, MROWS)            : adj row -> bf16 + denom rowsum
//   blocks [MROWS, MROWS+2048)   : nodes -> bf16
//   blocks [.., +64)             : W0 -> bf16
//   blocks [.., +64)             : Wr -> bf16
// ---------------------------------------------------------------------------
#define NB_NODES ((MROWS * DD) / (256 * 8))           // 2048
#define NB_W ((LL * DD * DD) / (256 * 8))             // 64

__global__ void convert_all_kernel(const float* __restrict__ adj,
                                   const float* __restrict__ nodes,
                                   const float* __restrict__ W0w,
                                   const float* __restrict__ Wrw) {
    int bid = blockIdx.x;
    int tid = threadIdx.x;

    if (bid < MROWS) {
        // adj row conversion + denom
        int row = bid;
        const float4* src = (const float4*)(adj + (size_t)row * NN);
        __nv_bfloat16* dst = g_adj_bf + (size_t)row * NN;
        float4 v0 = src[tid * 2 + 0];
        float4 v1 = src[tid * 2 + 1];
        float s = v0.x + v0.y + v0.z + v0.w + v1.x + v1.y + v1.z + v1.w;
        __nv_bfloat16 tmp[8];
        tmp[0] = __float2bfloat16(v0.x); tmp[1] = __float2bfloat16(v0.y);
        tmp[2] = __float2bfloat16(v0.z); tmp[3] = __float2bfloat16(v0.w);
        tmp[4] = __float2bfloat16(v1.x); tmp[5] = __float2bfloat16(v1.y);
        tmp[6] = __float2bfloat16(v1.z); tmp[7] = __float2bfloat16(v1.w);
        *(uint4*)(dst + tid * 8) = *(const uint4*)tmp;

        __shared__ float red[8];
#pragma unroll
        for (int o = 16; o; o >>= 1) s += __shfl_xor_sync(0xffffffffu, s, o);
        if ((tid & 31) == 0) red[tid >> 5] = s;
        __syncthreads();
        if (tid < 8) {
            float t = red[tid];
#pragma unroll
            for (int o = 4; o; o >>= 1) t += __shfl_xor_sync(0xffu, t, o);
            if (tid == 0) g_denom[row] = t + 1.0f;
        }
        return;
    }

    const float* src;
    __nv_bfloat16* dst;
    size_t off;
    int b2 = bid - MROWS;
    if (b2 < NB_NODES) {
        src = nodes; dst = g_nodes_bf; off = (size_t)b2 * 256 * 8;
    } else if (b2 < NB_NODES + NB_W) {
        src = W0w; dst = g_W0bf; off = (size_t)(b2 - NB_NODES) * 256 * 8;
    } else {
        src = Wrw; dst = g_Wrbf; off = (size_t)(b2 - NB_NODES - NB_W) * 256 * 8;
    }
    size_t p = off + (size_t)tid * 8;
    float4 v0 = *(const float4*)(src + p);
    float4 v1 = *(const float4*)(src + p + 4);
    __nv_bfloat16 tmp[8];
    tmp[0] = __float2bfloat16(v0.x); tmp[1] = __float2bfloat16(v0.y);
    tmp[2] = __float2bfloat16(v0.z); tmp[3] = __float2bfloat16(v0.w);
    tmp[4] = __float2bfloat16(v1.x); tmp[5] = __float2bfloat16(v1.y);
    tmp[6] = __float2bfloat16(v1.z); tmp[7] = __float2bfloat16(v1.w);
    *(uint4*)(dst + p) = *(const uint4*)tmp;
}

// ---------------------------------------------------------------------------
// Fused NT GEMM on mma.sync, persistent-B weights:
//   x@W0^T+b0 (fp32) and x@Wr^T+br (bf16, transposed)
//   B (weight 128x256 bf16) loaded ONCE into smem; A 2-stage cp.async.
//   grid = (4, 128), block = 256 (8 warps: 4M x 2N), 2 CTA/SM
// ---------------------------------------------------------------------------
__global__ void __launch_bounds__(256, 2)
xw_mma_kernel(int use_x,
              const float* __restrict__ b0,
              const float* __restrict__ br,
              int layer) {
    extern __shared__ char smem[];
    uint32_t sb = smem_u32(smem);
    __nv_bfloat16* Ts = (__nv_bfloat16*)smem;    // aliases A stages (epilogue only)

    int tid = threadIdx.x;
    int lane = tid & 31, wid = tid >> 5;
    int warp_m = wid & 3, warp_n = wid >> 2;
    int row0 = blockIdx.y * 128;
    int is_wr = (blockIdx.x >= 2);
    int colt = blockIdx.x & 1;
    int col0w = colt * 128;

    const __nv_bfloat16* Abase = use_x ? g_xbf : g_nodes_bf;
    const __nv_bfloat16* Ag = Abase + (size_t)row0 * DD;
    const __nv_bfloat16* Bg = (is_wr ? g_Wrbf : g_W0bf) + (size_t)layer * DD * DD
                              + (size_t)col0w * DD;

    float acc[2][8][4];
#pragma unroll
    for (int i = 0; i < 2; ++i)
#pragma unroll
        for (int j = 0; j < 8; ++j)
#pragma unroll
            for (int q = 0; q < 4; ++q) acc[i][j][q] = 0.f;

    uint32_t a_base = sb + (uint32_t)((warp_m * 32 + (lane & 15)) * ROWB + (lane >> 4) * 16);
    uint32_t b_base = sb + XW_B_OFF +
                      (uint32_t)((warp_n * 64 + (lane & 15)) * XW_B_STRIDE + (lane >> 4) * 16);

    // Persistent B load: 128 rows x 512B = 4096 x 16B, 16 per thread
    {
        uint32_t bs = sb + XW_B_OFF;
#pragma unroll
        for (int i = 0; i < 16; ++i) {
            int idx = i * 256 + tid;
            int r = idx >> 5, ch = idx & 31;
            cp_async16(bs + r * XW_B_STRIDE + ch * 16, Bg + (size_t)r * DD + ch * 8);
        }
        cp_commit();
    }

    auto ldA = [&](int c, int s) {
        uint32_t as = sb + s * XW_A_STAGE;
        int k0 = c * KC;
#pragma unroll
        for (int i = 0; i < 4; ++i) {
            int idx = i * 256 + tid;
            int r = idx >> 3, ch = idx & 7;
            cp_async16(as + r * ROWB + ch * 16, Ag + (size_t)r * DD + k0 + ch * 8);
        }
        cp_commit();
    };

    auto compute_stage = [&](int s, int c) {
        uint32_t as = a_base + s * XW_A_STAGE;
        uint32_t bs = b_base + c * 128;          // chunk K offset within B rows
#pragma unroll
        for (int ks = 0; ks < 4; ++ks) {
            uint32_t af[2][4];
            ldsm_x4(af[0], as + 0 * 16 * ROWB + ks * 32);
            ldsm_x4(af[1], as + 1 * 16 * ROWB + ks * 32);
            uint32_t bf[4][4];
#pragma unroll
            for (int n2 = 0; n2 < 4; ++n2)
                ldsm_x4(bf[n2], bs + n2 * 16 * XW_B_STRIDE + ks * 32);
#pragma unroll
            for (int mf = 0; mf < 2; ++mf)
#pragma unroll
                for (int nf = 0; nf < 8; ++nf)
                    mma_bf16(acc[mf][nf], af[mf], bf[nf >> 1][nf & 1],
                             bf[nf >> 1][(nf & 1) + 2]);
        }
    };

    ldA(0, 0);
    ldA(1, 1);
    for (int c = 0; c < 4; ++c) {
        if (c < 3) cp_wait<1>(); else cp_wait<0>();
        __syncthreads();
        compute_stage(c & 1, c);
        if (c + 2 < 4) {
            __syncthreads();                     // all warps done reading stage c&1
            ldA(c + 2, c & 1);
        }
    }

    const float* bias = (is_wr ? br : b0);
    int g = lane >> 2, tg = lane & 3;

    if (!is_wr) {
#pragma unroll
        for (int mf = 0; mf < 2; ++mf)
#pragma unroll
            for (int half = 0; half < 2; ++half) {
                int row = row0 + warp_m * 32 + mf * 16 + half * 8 + g;
#pragma unroll
                for (int nf = 0; nf < 8; ++nf) {
                    int col = col0w + warp_n * 64 + nf * 8 + tg * 2;
                    float2 bi = *(const float2*)(bias + col);
                    float2 r;
                    r.x = acc[mf][nf][half * 2 + 0] + bi.x;
                    r.y = acc[mf][nf][half * 2 + 1] + bi.y;
                    *(float2*)(g_xW0 + (size_t)row * DD + col) = r;
                }
            }
    } else {
        __syncthreads();     // A stages fully consumed; alias as Ts (34.8KB < 36.9KB)
#pragma unroll
        for (int mf = 0; mf < 2; ++mf)
#pragma unroll
            for (int half = 0; half < 2; ++half) {
                int rl = warp_m * 32 + mf * 16 + half * 8 + g;
#pragma unroll
                for (int nf = 0; nf < 8; ++nf) {
                    int cl = warp_n * 64 + nf * 8 + tg * 2;
                    float2 bi = *(const float2*)(bias + col0w + cl);
                    Ts[(size_t)cl * 136 + rl] =
                        __float2bfloat16(acc[mf][nf][half * 2 + 0] + bi.x);
                    Ts[(size_t)(cl + 1) * 136 + rl] =
                        __float2bfloat16(acc[mf][nf][half * 2 + 1] + bi.y);
                }
            }
        __syncthreads();
        int b = row0 >> 11;
        int nloc = row0 & 2047;
        int dl = tid >> 1, seg = tid & 1;
        __nv_bfloat16* dst = g_xWrT + (size_t)b * DD * NN + (size_t)(col0w + dl) * NN
                             + nloc + seg * 64;
        const __nv_bfloat16* srcp = Ts + (size_t)dl * 136 + seg * 64;
#pragma unroll
        for (int q = 0; q < 8; ++q)
            *(uint4*)(dst + q * 8) = *(const uint4*)(srcp + q * 8);
    }
}

// ---------------------------------------------------------------------------
// NN GEMM on mma.sync + fused epilogue (round-6 validated form, UNchanged)
//   grid = (DD/128=2, NN/128=16, BB=8) = 256 CTAs, 2 CTA/SM
// ---------------------------------------------------------------------------
#define NCHUNK (NN / KC)  // 32

__global__ void __launch_bounds__(256, 2)
nn_mma_kernel(const float* __restrict__ nodes, float* __restrict__ dout,
              int final_layer) {
    extern __shared__ char smem[];
    uint32_t sb = smem_u32(smem);

    int tid = threadIdx.x;
    int lane = tid & 31, wid = tid >> 5;
    int warp_m = wid & 3, warp_n = wid >> 2;
    int b = blockIdx.z;
    int row0 = blockIdx.y * 128;
    int col0 = blockIdx.x * 128;

    const __nv_bfloat16* Ag = g_adj_bf + (size_t)b * NN * NN + (size_t)row0 * NN;
    const __nv_bfloat16* Bg = g_xWrT + (size_t)b * DD * NN + (size_t)col0 * NN;

    float acc[2][8][4];
#pragma unroll
    for (int i = 0; i < 2; ++i)
#pragma unroll
        for (int j = 0; j < 8; ++j)
#pragma unroll
            for (int q = 0; q < 4; ++q) acc[i][j][q] = 0.f;

    uint32_t a_base = sb + (uint32_t)((warp_m * 32 + (lane & 15)) * ROWB + (lane >> 4) * 16);
    uint32_t b_base = sb + ASTAGE +
                      (uint32_t)((warp_n * 64 + (lane & 15)) * ROWB + (lane >> 4) * 16);

    auto load_stage = [&](int c, int s) {
        uint32_t as = sb + s * STAGE_BYTES;
        uint32_t bs = as + ASTAGE;
        int k0 = c * KC;
#pragma unroll
        for (int i = 0; i < 4; ++i) {
            int idx = i * 256 + tid;
            int r = idx >> 3, ch = idx & 7;
            cp_async16(as + r * ROWB + ch * 16, Ag + (size_t)r * NN + k0 + ch * 8);
        }
#pragma unroll
        for (int i = 0; i < 4; ++i) {
            int idx = i * 256 + tid;
            int r = idx >> 3, ch = idx & 7;
            cp_async16(bs + r * ROWB + ch * 16, Bg + (size_t)r * NN + k0 + ch * 8);
        }
        cp_commit();
    };

    auto compute_stage = [&](int s) {
        uint32_t as = a_base + s * STAGE_BYTES;
        uint32_t bs = b_base + s * STAGE_BYTES;
#pragma unroll
        for (int ks = 0; ks < 4; ++ks) {
            uint32_t af[2][4];
            ldsm_x4(af[0], as + 0 * 16 * ROWB + ks * 32);
            ldsm_x4(af[1], as + 1 * 16 * ROWB + ks * 32);
            uint32_t bf[4][4];
#pragma unroll
            for (int n2 = 0; n2 < 4; ++n2)
                ldsm_x4(bf[n2], bs + n2 * 16 * ROWB + ks * 32);
#pragma unroll
            for (int mf = 0; mf < 2; ++mf)
#pragma unroll
                for (int nf = 0; nf < 8; ++nf)
                    mma_bf16(acc[mf][nf], af[mf], bf[nf >> 1][nf & 1],
                             bf[nf >> 1][(nf & 1) + 2]);
        }
    };

    load_stage(0, 0);
    load_stage(1, 1);

    for (int c = 0; c < NCHUNK; ++c) {
        if (c + 1 < NCHUNK) cp_wait<1>(); else cp_wait<0>();
        __syncthreads();
        if (c + 2 < NCHUNK) load_stage(c + 2, (c + 2) % NSTAGES);
        compute_stage(c % NSTAGES);
    }

    int g = lane >> 2, tg = lane & 3;
#pragma unroll
    for (int mf = 0; mf < 2; ++mf) {
#pragma unroll
        for (int half = 0; half < 2; ++half) {
            int row = row0 + warp_m * 32 + mf * 16 + half * 8 + g;
            size_t grow = (size_t)b * NN + row;
            float inv = 1.0f / g_denom[grow];
            const float* w0r = g_xW0 + grow * DD;
            const float* ndr = nodes + grow * DD;
            float* orr = dout + grow * DD;
            __nv_bfloat16* xr = g_xbf + grow * DD;
#pragma unroll
            for (int nf = 0; nf < 8; ++nf) {
                int col = col0 + warp_n * 64 + nf * 8 + tg * 2;
                float2 w0 = *(const float2*)(w0r + col);
                float vx = fmaxf((acc[mf][nf][half * 2 + 0] + w0.x) * inv, 0.f);
                float vy = fmaxf((acc[mf][nf][half * 2 + 1] + w0.y) * inv, 0.f);
                if (final_layer) {
                    float2 nd = *(const float2*)(ndr + col);
                    vx += nd.x; vy += nd.y;
                    *(float2*)(orr + col) = make_float2(vx, vy);
                } else {
                    *(uint32_t*)(xr + col) = pack_bf16x2(vx, vy);
                }
            }
        }
    }
}

// ---------------------------------------------------------------------------
// Launch
// ---------------------------------------------------------------------------
extern "C" void kernel_launch(void* const* d_in, const int* in_sizes, int n_in,
                              void* d_out, int out_size) {
    const float* nodes = (const float*)d_in[0];
    const float* adj   = (const float*)d_in[1];
    const float* W0w   = (const float*)d_in[2];
    const float* W0b   = (const float*)d_in[3];
    const float* Wrw   = (const float*)d_in[4];
    const float* Wrb   = (const float*)d_in[5];
    float* out = (float*)d_out;

    cudaFuncSetAttribute(nn_mma_kernel, cudaFuncAttributeMaxDynamicSharedMemorySize,
                         NN_SMEM);
    cudaFuncSetAttribute(xw_mma_kernel, cudaFuncAttributeMaxDynamicSharedMemorySize,
                         XW_SMEM);

    convert_all_kernel<<<MROWS + NB_NODES + 2 * NB_W, 256>>>(adj, nodes, W0w, Wrw);

    dim3 grid_xw(4, MROWS / 128);          // (4, 128)
    dim3 grid_nn(DD / 128, NN / 128, BB);  // (2, 16, 8)

    for (int l = 0; l < LL; ++l) {
        xw_mma_kernel<<<grid_xw, 256, XW_SMEM>>>((l == 0) ? 0 : 1,
                                                 W0b + (size_t)l * DD,
                                                 Wrb + (size_t)l * DD, l);
        nn_mma_kernel<<<grid_nn, 256, NN_SMEM>>>(nodes, out, (l == LL - 1) ? 1 : 0);
    }
}

// round 9
// speedup vs baseline: 1.0998x; 1.0567x over previous
#include <cuda_runtime.h>
#include <cuda_bf16.h>
#include <cstdint>

// Problem constants
#define BB 8
#define NN 2048
#define DD 256
#define LL 2
#define MROWS (BB * NN)   // 16384

#define KC 64             // K per pipeline chunk
#define NSTAGES 3

// smem geometry (padded, no swizzle) — shared by both MMA kernels
#define PADK 72                      // 64 + 8 bf16 pad
#define ROWB (PADK * 2)              // 144 bytes per row
#define ASTAGE (128 * ROWB)          // 18432 B
#define STAGE_BYTES (2 * ASTAGE)     // 36864 B (A + B)
#define MMA_SMEM (NSTAGES * STAGE_BYTES)  // 110592 B

// ---------------------------------------------------------------------------
// Scratch (static __device__ arrays — no allocation allowed)
// ---------------------------------------------------------------------------
__device__ __nv_bfloat16 g_adj_bf[(size_t)BB * NN * NN];    // adj bf16
__device__ __nv_bfloat16 g_nodes_bf[(size_t)MROWS * DD];    // nodes bf16 (plain)
__device__ __nv_bfloat16 g_xbf[(size_t)MROWS * DD];         // activations bf16 (plain)
__device__ __nv_bfloat16 g_xT[(size_t)BB * DD * NN];        // x transposed [b][d][n]
__device__ __nv_bfloat16 g_S[(size_t)MROWS * DD];           // S = adj @ x (bf16)
__device__ __nv_bfloat16 g_W0bf[(size_t)LL * DD * DD];      // W0_w bf16
__device__ __nv_bfloat16 g_Wrbf[(size_t)LL * DD * DD];      // Wr_w bf16
__device__ float g_denom[MROWS];                            // row-sum(adj) + 1

// ---------------------------------------------------------------------------
// PTX helpers (plain-sm_103-safe)
// ---------------------------------------------------------------------------
__device__ __forceinline__ uint32_t smem_u32(const void* p) {
    uint32_t a;
    asm("{ .reg .u64 t; cvta.to.shared.u64 t, %1; cvt.u32.u64 %0, t; }" : "=r"(a) : "l"(p));
    return a;
}
__device__ __forceinline__ void cp_async16(uint32_t saddr, const void* g) {
    asm volatile("cp.async.cg.shared.global [%0], [%1], 16;" :: "r"(saddr), "l"(g) : "memory");
}
__device__ __forceinline__ void cp_commit() {
    asm volatile("cp.async.commit_group;" ::: "memory");
}
template <int N>
__device__ __forceinline__ void cp_wait() {
    asm volatile("cp.async.wait_group %0;" :: "n"(N) : "memory");
}
__device__ __forceinline__ void ldsm_x4(uint32_t (&r)[4], uint32_t addr) {
    asm volatile("ldmatrix.sync.aligned.m8n8.x4.shared.b16 {%0,%1,%2,%3}, [%4];"
                 : "=r"(r[0]), "=r"(r[1]), "=r"(r[2]), "=r"(r[3]) : "r"(addr));
}
__device__ __forceinline__ void mma_bf16(float (&c)[4], const uint32_t (&a)[4],
                                         uint32_t b0, uint32_t b1) {
    asm volatile(
        "mma.sync.aligned.m16n8k16.row.col.f32.bf16.bf16.f32 "
        "{%0,%1,%2,%3}, {%4,%5,%6,%7}, {%8,%9}, {%0,%1,%2,%3};"
        : "+f"(c[0]), "+f"(c[1]), "+f"(c[2]), "+f"(c[3])
        : "r"(a[0]), "r"(a[1]), "r"(a[2]), "r"(a[3]), "r"(b0), "r"(b1));
}
__device__ __forceinline__ uint32_t pack_bf16x2(float x, float y) {
    __nv_bfloat162 v = __floats2bfloat162_rn(x, y);
    return *(uint32_t*)&v;
}

// ---------------------------------------------------------------------------
// One conversion kernel: adj->bf16 + denom, nodes->bf16, weights->bf16
// ---------------------------------------------------------------------------
#define NB_NODES ((MROWS * DD) / (256 * 8))           // 2048
#define NB_W ((LL * DD * DD) / (256 * 8))             // 64

__global__ void convert_all_kernel(const float* __restrict__ adj,
                                   const float* __restrict__ nodes,
                                   const float* __restrict__ W0w,
                                   const float* __restrict__ Wrw) {
    int bid = blockIdx.x;
    int tid = threadIdx.x;

    if (bid < MROWS) {
        int row = bid;
        const float4* src = (const float4*)(adj + (size_t)row * NN);
        __nv_bfloat16* dst = g_adj_bf + (size_t)row * NN;
        float4 v0 = src[tid * 2 + 0];
        float4 v1 = src[tid * 2 + 1];
        float s = v0.x + v0.y + v0.z + v0.w + v1.x + v1.y + v1.z + v1.w;
        __nv_bfloat16 tmp[8];
        tmp[0] = __float2bfloat16(v0.x); tmp[1] = __float2bfloat16(v0.y);
        tmp[2] = __float2bfloat16(v0.z); tmp[3] = __float2bfloat16(v0.w);
        tmp[4] = __float2bfloat16(v1.x); tmp[5] = __float2bfloat16(v1.y);
        tmp[6] = __float2bfloat16(v1.z); tmp[7] = __float2bfloat16(v1.w);
        *(uint4*)(dst + tid * 8) = *(const uint4*)tmp;

        __shared__ float red[8];
#pragma unroll
        for (int o = 16; o; o >>= 1) s += __shfl_xor_sync(0xffffffffu, s, o);
        if ((tid & 31) == 0) red[tid >> 5] = s;
        __syncthreads();
        if (tid < 8) {
            float t = red[tid];
#pragma unroll
            for (int o = 4; o; o >>= 1) t += __shfl_xor_sync(0xffu, t, o);
            if (tid == 0) g_denom[row] = t + 1.0f;
        }
        return;
    }

    const float* src;
    __nv_bfloat16* dst;
    size_t off;
    int b2 = bid - MROWS;
    if (b2 < NB_NODES) {
        src = nodes; dst = g_nodes_bf; off = (size_t)b2 * 256 * 8;
    } else if (b2 < NB_NODES + NB_W) {
        src = W0w; dst = g_W0bf; off = (size_t)(b2 - NB_NODES) * 256 * 8;
    } else {
        src = Wrw; dst = g_Wrbf; off = (size_t)(b2 - NB_NODES - NB_W) * 256 * 8;
    }
    size_t p = off + (size_t)tid * 8;
    float4 v0 = *(const float4*)(src + p);
    float4 v1 = *(const float4*)(src + p + 4);
    __nv_bfloat16 tmp[8];
    tmp[0] = __float2bfloat16(v0.x); tmp[1] = __float2bfloat16(v0.y);
    tmp[2] = __float2bfloat16(v0.z); tmp[3] = __float2bfloat16(v0.w);
    tmp[4] = __float2bfloat16(v1.x); tmp[5] = __float2bfloat16(v1.y);
    tmp[6] = __float2bfloat16(v1.z); tmp[7] = __float2bfloat16(v1.w);
    *(uint4*)(dst + p) = *(const uint4*)tmp;
}

// ---------------------------------------------------------------------------
// transpose nodes_bf [b*2048+n][256] -> g_xT [b][d][n]   (layer-0 nn B operand)
//   grid (2 d-tiles, 16 n-tiles, 8 b), block 256, 128x128 smem tile
// ---------------------------------------------------------------------------
__global__ void transpose_nodes_kernel() {
    __shared__ __nv_bfloat16 sm[128 * 144];
    int tid = threadIdx.x;
    int dt = blockIdx.x, nt = blockIdx.y, b = blockIdx.z;

#pragma unroll
    for (int i = 0; i < 8; ++i) {
        int idx = i * 256 + tid;
        int r = idx >> 4, ch = idx & 15;          // r = n-row, ch = 16B chunk of d
        const __nv_bfloat16* src = g_nodes_bf +
            ((size_t)b * NN + nt * 128 + r) * DD + dt * 128 + ch * 8;
        *(uint4*)&sm[r * 144 + ch * 8] = *(const uint4*)src;
    }
    __syncthreads();
#pragma unroll
    for (int i = 0; i < 8; ++i) {
        int idx = i * 256 + tid;
        int d = idx >> 4, ch = idx & 15;          // d = output row, ch = n chunk
        __nv_bfloat16 tmp[8];
#pragma unroll
        for (int j = 0; j < 8; ++j) tmp[j] = sm[(ch * 8 + j) * 144 + d];
        *(uint4*)(g_xT + (size_t)b * DD * NN + (size_t)(dt * 128 + d) * NN
                  + nt * 128 + ch * 8) = *(const uint4*)tmp;
    }
}

// ---------------------------------------------------------------------------
// Big GEMM: S = adj @ x   (B = g_xT, K-major — same layout as old xWrT)
//   Epilogue: raw bf16 store of S. grid (2, 16, 8), block 256, 2 CTA/SM
// ---------------------------------------------------------------------------
#define NCHUNK (NN / KC)  // 32

__global__ void __launch_bounds__(256, 2)
nn_mma_kernel() {
    extern __shared__ char smem[];
    uint32_t sb = smem_u32(smem);

    int tid = threadIdx.x;
    int lane = tid & 31, wid = tid >> 5;
    int warp_m = wid & 3, warp_n = wid >> 2;
    int b = blockIdx.z;
    int row0 = blockIdx.y * 128;
    int col0 = blockIdx.x * 128;

    const __nv_bfloat16* Ag = g_adj_bf + (size_t)b * NN * NN + (size_t)row0 * NN;
    const __nv_bfloat16* Bg = g_xT + (size_t)b * DD * NN + (size_t)col0 * NN;

    float acc[2][8][4];
#pragma unroll
    for (int i = 0; i < 2; ++i)
#pragma unroll
        for (int j = 0; j < 8; ++j)
#pragma unroll
            for (int q = 0; q < 4; ++q) acc[i][j][q] = 0.f;

    uint32_t a_base = sb + (uint32_t)((warp_m * 32 + (lane & 15)) * ROWB + (lane >> 4) * 16);
    uint32_t b_base = sb + ASTAGE +
                      (uint32_t)((warp_n * 64 + (lane & 15)) * ROWB + (lane >> 4) * 16);

    auto load_stage = [&](int c, int s) {
        uint32_t as = sb + s * STAGE_BYTES;
        uint32_t bs = as + ASTAGE;
        int k0 = c * KC;
#pragma unroll
        for (int i = 0; i < 4; ++i) {
            int idx = i * 256 + tid;
            int r = idx >> 3, ch = idx & 7;
            cp_async16(as + r * ROWB + ch * 16, Ag + (size_t)r * NN + k0 + ch * 8);
        }
#pragma unroll
        for (int i = 0; i < 4; ++i) {
            int idx = i * 256 + tid;
            int r = idx >> 3, ch = idx & 7;
            cp_async16(bs + r * ROWB + ch * 16, Bg + (size_t)r * NN + k0 + ch * 8);
        }
        cp_commit();
    };

    auto compute_stage = [&](int s) {
        uint32_t as = a_base + s * STAGE_BYTES;
        uint32_t bs = b_base + s * STAGE_BYTES;
#pragma unroll
        for (int ks = 0; ks < 4; ++ks) {
            uint32_t af[2][4];
            ldsm_x4(af[0], as + 0 * 16 * ROWB + ks * 32);
            ldsm_x4(af[1], as + 1 * 16 * ROWB + ks * 32);
            uint32_t bf[4][4];
#pragma unroll
            for (int n2 = 0; n2 < 4; ++n2)
                ldsm_x4(bf[n2], bs + n2 * 16 * ROWB + ks * 32);
#pragma unroll
            for (int mf = 0; mf < 2; ++mf)
#pragma unroll
                for (int nf = 0; nf < 8; ++nf)
                    mma_bf16(acc[mf][nf], af[mf], bf[nf >> 1][nf & 1],
                             bf[nf >> 1][(nf & 1) + 2]);
        }
    };

    load_stage(0, 0);
    load_stage(1, 1);

    for (int c = 0; c < NCHUNK; ++c) {
        if (c + 1 < NCHUNK) cp_wait<1>(); else cp_wait<0>();
        __syncthreads();
        if (c + 2 < NCHUNK) load_stage(c + 2, (c + 2) % NSTAGES);
        compute_stage(c % NSTAGES);
    }

    // epilogue: raw bf16 store of S
    int g = lane >> 2, tg = lane & 3;
#pragma unroll
    for (int mf = 0; mf < 2; ++mf) {
#pragma unroll
        for (int half = 0; half < 2; ++half) {
            int row = row0 + warp_m * 32 + mf * 16 + half * 8 + g;
            size_t grow = (size_t)b * NN + row;
#pragma unroll
            for (int nf = 0; nf < 8; ++nf) {
                int col = col0 + warp_n * 64 + nf * 8 + tg * 2;
                *(uint32_t*)(g_S + grow * DD + col) =
                    pack_bf16x2(acc[mf][nf][half * 2 + 0], acc[mf][nf][half * 2 + 1]);
            }
        }
    }
}

// ---------------------------------------------------------------------------
// epi kernel: acc = S@Wr^T + x@W0^T   (two K=256 passes, 8 chunks, 3-stage)
//   out = relu((acc + b0 + (denom-1)*br) / denom)
//   final: dout = nodes + out (fp32); else: g_xbf (plain) + g_xT (transposed)
//   grid (2, 128), block 256, 2 CTA/SM
// ---------------------------------------------------------------------------
__global__ void __launch_bounds__(256, 2)
epi_mma_kernel(int use_x,
               const float* __restrict__ b0,
               const float* __restrict__ br,
               const float* __restrict__ nodes,
               float* __restrict__ dout,
               int layer, int final_layer) {
    extern __shared__ char smem[];
    uint32_t sb = smem_u32(smem);
    __nv_bfloat16* Ts = (__nv_bfloat16*)smem;    // aliases stage mem (epilogue only)

    int tid = threadIdx.x;
    int lane = tid & 31, wid = tid >> 5;
    int warp_m = wid & 3, warp_n = wid >> 2;
    int row0 = blockIdx.y * 128;
    int col0w = blockIdx.x * 128;                // output feature tile

    const __nv_bfloat16* A0 = g_S + (size_t)row0 * DD;
    const __nv_bfloat16* A1 = (use_x ? g_xbf : g_nodes_bf) + (size_t)row0 * DD;
    const __nv_bfloat16* B0 = g_Wrbf + (size_t)layer * DD * DD + (size_t)col0w * DD;
    const __nv_bfloat16* B1 = g_W0bf + (size_t)layer * DD * DD + (size_t)col0w * DD;

    float acc[2][8][4];
#pragma unroll
    for (int i = 0; i < 2; ++i)
#pragma unroll
        for (int j = 0; j < 8; ++j)
#pragma unroll
            for (int q = 0; q < 4; ++q) acc[i][j][q] = 0.f;

    uint32_t a_base = sb + (uint32_t)((warp_m * 32 + (lane & 15)) * ROWB + (lane >> 4) * 16);
    uint32_t b_base = sb + ASTAGE +
                      (uint32_t)((warp_n * 64 + (lane & 15)) * ROWB + (lane >> 4) * 16);

    // chunk c in [0,8): c<4 -> (S, Wr) pass; c>=4 -> (x, W0) pass
    auto load_stage = [&](int c, int s) {
        uint32_t as = sb + s * STAGE_BYTES;
        uint32_t bs = as + ASTAGE;
        const __nv_bfloat16* Ag = (c < 4) ? A0 : A1;
        const __nv_bfloat16* Bg = (c < 4) ? B0 : B1;
        int k0 = (c & 3) * KC;
#pragma unroll
        for (int i = 0; i < 4; ++i) {
            int idx = i * 256 + tid;
            int r = idx >> 3, ch = idx & 7;
            cp_async16(as + r * ROWB + ch * 16, Ag + (size_t)r * DD + k0 + ch * 8);
        }
#pragma unroll
        for (int i = 0; i < 4; ++i) {
            int idx = i * 256 + tid;
            int r = idx >> 3, ch = idx & 7;
            cp_async16(bs + r * ROWB + ch * 16, Bg + (size_t)r * DD + k0 + ch * 8);
        }
        cp_commit();
    };

    auto compute_stage = [&](int s) {
        uint32_t as = a_base + s * STAGE_BYTES;
        uint32_t bs = b_base + s * STAGE_BYTES;
#pragma unroll
        for (int ks = 0; ks < 4; ++ks) {
            uint32_t af[2][4];
            ldsm_x4(af[0], as + 0 * 16 * ROWB + ks * 32);
            ldsm_x4(af[1], as + 1 * 16 * ROWB + ks * 32);
            uint32_t bf[4][4];
#pragma unroll
            for (int n2 = 0; n2 < 4; ++n2)
                ldsm_x4(bf[n2], bs + n2 * 16 * ROWB + ks * 32);
#pragma unroll
            for (int mf = 0; mf < 2; ++mf)
#pragma unroll
                for (int nf = 0; nf < 8; ++nf)
                    mma_bf16(acc[mf][nf], af[mf], bf[nf >> 1][nf & 1],
                             bf[nf >> 1][(nf & 1) + 2]);
        }
    };

    load_stage(0, 0);
    load_stage(1, 1);
    for (int c = 0; c < 8; ++c) {
        if (c + 1 < 8) cp_wait<1>(); else cp_wait<0>();
        __syncthreads();
        if (c + 2 < 8) load_stage(c + 2, (c + 2) % NSTAGES);
        compute_stage(c % NSTAGES);
    }

    int g = lane >> 2, tg = lane & 3;

    if (final_layer) {
#pragma unroll
        for (int mf = 0; mf < 2; ++mf)
#pragma unroll
            for (int half = 0; half < 2; ++half) {
                int rl = warp_m * 32 + mf * 16 + half * 8 + g;
                size_t grow = (size_t)row0 + rl;
                float den = g_denom[grow];
                float inv = 1.0f / den;
                float rs = den - 1.0f;
#pragma unroll
                for (int nf = 0; nf < 8; ++nf) {
                    int m = col0w + warp_n * 64 + nf * 8 + tg * 2;
                    float2 bi0 = *(const float2*)(b0 + m);
                    float2 bir = *(const float2*)(br + m);
                    float vx = fmaxf((acc[mf][nf][half * 2 + 0] + bi0.x + rs * bir.x) * inv, 0.f);
                    float vy = fmaxf((acc[mf][nf][half * 2 + 1] + bi0.y + rs * bir.y) * inv, 0.f);
                    float2 nd = *(const float2*)(nodes + grow * DD + m);
                    *(float2*)(dout + grow * DD + m) = make_float2(vx + nd.x, vy + nd.y);
                }
            }
    } else {
        __syncthreads();     // stage smem fully consumed; safe to alias as Ts
#pragma unroll
        for (int mf = 0; mf < 2; ++mf)
#pragma unroll
            for (int half = 0; half < 2; ++half) {
                int rl = warp_m * 32 + mf * 16 + half * 8 + g;
                size_t grow = (size_t)row0 + rl;
                float den = g_denom[grow];
                float inv = 1.0f / den;
                float rs = den - 1.0f;
#pragma unroll
                for (int nf = 0; nf < 8; ++nf) {
                    int cl = warp_n * 64 + nf * 8 + tg * 2;
                    int m = col0w + cl;
                    float2 bi0 = *(const float2*)(b0 + m);
                    float2 bir = *(const float2*)(br + m);
                    float vx = fmaxf((acc[mf][nf][half * 2 + 0] + bi0.x + rs * bir.x) * inv, 0.f);
                    float vy = fmaxf((acc[mf][nf][half * 2 + 1] + bi0.y + rs * bir.y) * inv, 0.f);
                    // plain write (next epi's A operand)
                    *(uint32_t*)(g_xbf + grow * DD + m) = pack_bf16x2(vx, vy);
                    // transposed staging (next nn's B operand)
                    Ts[(size_t)cl * 136 + rl] = __float2bfloat16(vx);
                    Ts[(size_t)(cl + 1) * 136 + rl] = __float2bfloat16(vy);
                }
            }
        __syncthreads();
        int b = row0 >> 11;
        int nloc = row0 & 2047;
        int dl = tid >> 1, seg = tid & 1;
        __nv_bfloat16* dst = g_xT + (size_t)b * DD * NN + (size_t)(col0w + dl) * NN
                             + nloc + seg * 64;
        const __nv_bfloat16* srcp = Ts + (size_t)dl * 136 + seg * 64;
#pragma unroll
        for (int q = 0; q < 8; ++q)
            *(uint4*)(dst + q * 8) = *(const uint4*)(srcp + q * 8);
    }
}

// ---------------------------------------------------------------------------
// Launch
// ---------------------------------------------------------------------------
extern "C" void kernel_launch(void* const* d_in, const int* in_sizes, int n_in,
                              void* d_out, int out_size) {
    const float* nodes = (const float*)d_in[0];
    const float* adj   = (const float*)d_in[1];
    const float* W0w   = (const float*)d_in[2];
    const float* W0b   = (const float*)d_in[3];
    const float* Wrw   = (const float*)d_in[4];
    const float* Wrb   = (const float*)d_in[5];
    float* out = (float*)d_out;

    cudaFuncSetAttribute(nn_mma_kernel, cudaFuncAttributeMaxDynamicSharedMemorySize,
                         MMA_SMEM);
    cudaFuncSetAttribute(epi_mma_kernel, cudaFuncAttributeMaxDynamicSharedMemorySize,
                         MMA_SMEM);

    convert_all_kernel<<<MROWS + NB_NODES + 2 * NB_W, 256>>>(adj, nodes, W0w, Wrw);

    dim3 grid_tr(2, 16, 8);                // nodes -> g_xT
    transpose_nodes_kernel<<<grid_tr, 256>>>();

    dim3 grid_nn(DD / 128, NN / 128, BB);  // (2, 16, 8)
    dim3 grid_epi(2, MROWS / 128);         // (2, 128)

    for (int l = 0; l < LL; ++l) {
        nn_mma_kernel<<<grid_nn, 256, MMA_SMEM>>>();   // S = adj @ x_l
        epi_mma_kernel<<<grid_epi, 256, MMA_SMEM>>>(
            (l == 0) ? 0 : 1,
            W0b + (size_t)l * DD, Wrb + (size_t)l * DD,
            nodes, out, l, (l == LL - 1) ? 1 : 0);
    }
}